// round 15
// baseline (speedup 1.0000x reference)
#include <cuda_runtime.h>
#include <cuda_fp16.h>
#include <cstdint>

#define SLEN 2048
#define BSZ  2
#define EMB  1024
#define NH   16
#define DHD  64
#define PFW  16
#define MTOK (SLEN*BSZ)
#define GBK  32              // K per chunk
#define NCHUNK (EMB/GBK)     // 32
#define GBM  128
#define GBN  256
#define STAGES 4
#define ROWB 80              // padded smem row bytes (64 data + 16 pad)
#define SROWS 384            // A 128 rows + B 256 rows
#define STGB (SROWS*ROWB)    // 30720
#define GEMM_SMEM (STAGES*STGB)  // 122880
#define GTHR 512
#define NQKV 3072
#define KROWB 144            // attn K/V smem row pitch (128 data + 16 pad)
#define KV_BYTES (2*32*KROWB)    // 9216 per warp (K 32 rows + V 32 rows)
#define ATTN_SMEM (16*KV_BYTES)  // 147456
// O-proj f16-accum GEMM tile
#define OBM 128
#define OBN 128
#define OSROWS 256           // A 128 + B 128 rows
#define OSTGB (OSROWS*ROWB)  // 20480
#define OSMEM (STAGES*OSTGB) // 81920

// ---------------- scratch (static device arrays; no allocation) -------------
__device__ __align__(16) __half g_xn [MTOK*EMB];        // LN out fp16
__device__ __align__(16) __half g_att[MTOK*EMB];        // attn out fp16
__device__ __align__(16) __half g_wh [4*EMB*EMB];       // Wq|Wk|Wv|Wo fp16, [N][K]
__device__ __align__(16) __half g_qkv[MTOK*NQKV];       // fused QKV output (fp16)
__device__ float g_bias[NQKV];

// ---------------- PTX helpers ------------------------------------------------
__device__ __forceinline__ uint32_t s2u(const void* p) {
    uint32_t a;
    asm("{ .reg .u64 t; cvta.to.shared.u64 t, %1; cvt.u32.u64 %0, t; }" : "=r"(a) : "l"(p));
    return a;
}
__device__ __forceinline__ void cp16(uint32_t dst, const void* src) {
    asm volatile("cp.async.cg.shared.global [%0], [%1], 16;" :: "r"(dst), "l"(src));
}
#define CP_COMMIT() asm volatile("cp.async.commit_group;" ::: "memory")

__device__ __forceinline__ void ldsm4(uint32_t* r, uint32_t addr) {
    asm volatile("ldmatrix.sync.aligned.m8n8.x4.shared.b16 {%0,%1,%2,%3}, [%4];"
        : "=r"(r[0]), "=r"(r[1]), "=r"(r[2]), "=r"(r[3]) : "r"(addr));
}
__device__ __forceinline__ void ldsm4t(uint32_t* r, uint32_t addr) {
    asm volatile("ldmatrix.sync.aligned.m8n8.x4.trans.shared.b16 {%0,%1,%2,%3}, [%4];"
        : "=r"(r[0]), "=r"(r[1]), "=r"(r[2]), "=r"(r[3]) : "r"(addr));
}
__device__ __forceinline__ void mma16816(float* d, const uint32_t* a,
                                         uint32_t b0, uint32_t b1) {
    asm volatile("mma.sync.aligned.m16n8k16.row.col.f32.f16.f16.f32 "
        "{%0,%1,%2,%3}, {%4,%5,%6,%7}, {%8,%9}, {%0,%1,%2,%3};"
        : "+f"(d[0]), "+f"(d[1]), "+f"(d[2]), "+f"(d[3])
        : "r"(a[0]), "r"(a[1]), "r"(a[2]), "r"(a[3]), "r"(b0), "r"(b1));
}
__device__ __forceinline__ void mma16816h(uint32_t* d, const uint32_t* a,
                                          uint32_t b0, uint32_t b1) {
    asm volatile("mma.sync.aligned.m16n8k16.row.col.f16.f16.f16.f16 "
        "{%0,%1}, {%2,%3,%4,%5}, {%6,%7}, {%0,%1};"
        : "+r"(d[0]), "+r"(d[1])
        : "r"(a[0]), "r"(a[1]), "r"(a[2]), "r"(a[3]), "r"(b0), "r"(b1));
}

// ---------------- merged prep: wprep (blocks 0..4095) + LN (4096..8191)
//                  + bias concat (8192..8203), one launch --------------------
__global__ void __launch_bounds__(256) prep_kernel(
    const float* __restrict__ x,
    const float* __restrict__ gamma,
    const float* __restrict__ beta,
    const float* __restrict__ W0, const float* __restrict__ W1,
    const float* __restrict__ W2, const float* __restrict__ W3,
    const float* __restrict__ bq, const float* __restrict__ bk,
    const float* __restrict__ bv,
    __half* __restrict__ Bh,
    __half* __restrict__ xn,
    float* __restrict__ bqkv)
{
    int bid = blockIdx.x;
    int tid = threadIdx.x;

    if (bid < 4096) {
        int wsel = bid >> 10;
        int t = bid & 1023;
        int n0 = (t & 31) * 32;
        int k0 = (t >> 5) * 32;
        const float* W = (wsel == 0) ? W0 : (wsel == 1) ? W1
                       : (wsel == 2) ? W2 : W3;
        __half* B = Bh + (size_t)wsel * EMB * EMB;
        __shared__ float tile[32][33];
        int tx = tid & 31;
        int ty = tid >> 5;
        #pragma unroll
        for (int r = ty; r < 32; r += 8)
            tile[r][tx] = W[(size_t)(k0 + r) * EMB + n0 + tx];
        __syncthreads();
        #pragma unroll
        for (int r = ty; r < 32; r += 8)
            B[(size_t)(n0 + r) * EMB + (k0 + tx)] = __float2half(tile[tx][r]);
    } else if (bid < 8192) {
        int row = bid - 4096;
        const float4 xv = ((const float4*)(x + (size_t)row * EMB))[tid];
        float s  = xv.x + xv.y + xv.z + xv.w;
        float s2 = xv.x*xv.x + xv.y*xv.y + xv.z*xv.z + xv.w*xv.w;
        #pragma unroll
        for (int o = 16; o > 0; o >>= 1) {
            s  += __shfl_xor_sync(0xffffffffu, s,  o);
            s2 += __shfl_xor_sync(0xffffffffu, s2, o);
        }
        __shared__ float rs[8], rs2[8];
        __shared__ float mean_s, rstd_s;
        int w = tid >> 5, l = tid & 31;
        if (l == 0) { rs[w] = s; rs2[w] = s2; }
        __syncthreads();
        if (tid == 0) {
            float ts = 0.f, ts2 = 0.f;
            #pragma unroll
            for (int i = 0; i < 8; i++) { ts += rs[i]; ts2 += rs2[i]; }
            float mean = ts * (1.0f / EMB);
            float var  = ts2 * (1.0f / EMB) - mean * mean;
            mean_s = mean;
            rstd_s = rsqrtf(var + 1e-5f);
        }
        __syncthreads();
        float mean = mean_s, r = rstd_s;
        float4 gv = ((const float4*)gamma)[tid];
        float4 bv2 = ((const float4*)beta)[tid];
        __half h[4];
        h[0] = __float2half((xv.x - mean) * r * gv.x + bv2.x);
        h[1] = __float2half((xv.y - mean) * r * gv.y + bv2.y);
        h[2] = __float2half((xv.z - mean) * r * gv.z + bv2.z);
        h[3] = __float2half((xv.w - mean) * r * gv.w + bv2.w);
        *(uint2*)(xn + (size_t)row * EMB + tid * 4) = *(uint2*)h;
    } else {
        int i = (bid - 8192) * 256 + tid;
        if (i < NQKV)
            bqkv[i] = (i < EMB) ? bq[i] : (i < 2*EMB) ? bk[i - EMB] : bv[i - 2*EMB];
    }
}

// ---------------- HMMA fp16 GEMM (fp32 accum): C = A @ B^T + bias ----------
template<int OUT_HALF>
__global__ void __launch_bounds__(GTHR, 1) gemm_mma(
    const __half* __restrict__ A,
    const __half* __restrict__ B,
    const float* __restrict__ bias,
    const float* __restrict__ res,
    void* __restrict__ Cv,
    int ldc)
{
    extern __shared__ char smem[];
    uint32_t sb = s2u(smem);
    int tid = threadIdx.x;
    int w = tid >> 5, l = tid & 31;
    int bm = blockIdx.y * GBM;
    int bn = blockIdx.x * GBN;
    int wm = (w & 3) * 32;
    int wn = (w >> 2) * 64;

    int r0 = tid >> 2;
    int ch = tid & 3;
    const __half* p0 = A + (size_t)(bm + r0) * EMB + ch * 8;
    const __half* p1 = B + (size_t)(bn + r0) * EMB + ch * 8;
    const __half* p2 = B + (size_t)(bn + r0 + 128) * EMB + ch * 8;
    uint32_t d0 = (uint32_t)r0 * ROWB + ch * 16;
    uint32_t d1 = d0 + 128 * ROWB;
    uint32_t d2 = d0 + 256 * ROWB;

    float acc[2][8][4];
    #pragma unroll
    for (int i = 0; i < 2; i++)
        #pragma unroll
        for (int j = 0; j < 8; j++)
            #pragma unroll
            for (int t = 0; t < 4; t++) acc[i][j][t] = 0.f;

    #pragma unroll
    for (int c = 0; c < STAGES - 1; c++) {
        uint32_t stg = sb + c * STGB;
        cp16(stg + d0, p0); p0 += GBK;
        cp16(stg + d1, p1); p1 += GBK;
        cp16(stg + d2, p2); p2 += GBK;
        CP_COMMIT();
    }

    uint32_t arow = (uint32_t)(wm + (l & 15)) * ROWB + ((l >> 4) << 4);
    uint32_t brow = (uint32_t)(128 + wn + (l & 15)) * ROWB + ((l >> 4) << 4);

    for (int c0 = 0; c0 < NCHUNK; c0 += STAGES) {
        #pragma unroll
        for (int s = 0; s < STAGES; s++) {
            int c = c0 + s;
            asm volatile("cp.async.wait_group %0;" :: "n"(STAGES - 2) : "memory");
            __syncthreads();
            uint32_t stg = sb + (uint32_t)s * STGB;

            if (c + STAGES - 1 < NCHUNK) {
                uint32_t ds = sb + (uint32_t)(((unsigned)(s + STAGES - 1)) & (STAGES - 1)) * STGB;
                cp16(ds + d0, p0); p0 += GBK;
                cp16(ds + d1, p1); p1 += GBK;
                cp16(ds + d2, p2); p2 += GBK;
            }
            CP_COMMIT();

            uint32_t sA = stg + arow;
            uint32_t sB = stg + brow;

            #pragma unroll
            for (int ks = 0; ks < 2; ks++) {
                uint32_t af[2][4], br[4][4];
                #pragma unroll
                for (int mt = 0; mt < 2; mt++)
                    ldsm4(af[mt], sA + mt * (16 * ROWB) + ks * 32);
                #pragma unroll
                for (int bt = 0; bt < 4; bt++)
                    ldsm4(br[bt], sB + bt * (16 * ROWB) + ks * 32);
                #pragma unroll
                for (int mt = 0; mt < 2; mt++)
                    #pragma unroll
                    for (int bt = 0; bt < 4; bt++) {
                        mma16816(acc[mt][2 * bt],     af[mt], br[bt][0], br[bt][2]);
                        mma16816(acc[mt][2 * bt + 1], af[mt], br[bt][1], br[bt][3]);
                    }
            }
        }
    }

    int rbase = bm + wm + (l >> 2);
    int cbase = bn + wn + 2 * (l & 3);
    #pragma unroll
    for (int mt = 0; mt < 2; mt++) {
        #pragma unroll
        for (int nt = 0; nt < 8; nt++) {
            int col = cbase + nt * 8;
            float bx = bias[col], by = bias[col + 1];
            int rr0 = rbase + mt * 16;
            int rr1 = rr0 + 8;
            float v0x = acc[mt][nt][0] + bx;
            float v0y = acc[mt][nt][1] + by;
            float v1x = acc[mt][nt][2] + bx;
            float v1y = acc[mt][nt][3] + by;
            if (OUT_HALF) {
                __half* C = (__half*)Cv;
                *(__half2*)(C + (size_t)rr0 * ldc + col) = __floats2half2_rn(v0x, v0y);
                *(__half2*)(C + (size_t)rr1 * ldc + col) = __floats2half2_rn(v1x, v1y);
            } else {
                float* C = (float*)Cv;
                float2 q0 = *(const float2*)(res + (size_t)rr0 * EMB + col);
                float2 q1 = *(const float2*)(res + (size_t)rr1 * EMB + col);
                float2 o0 = {v0x + q0.x, v0y + q0.y};
                float2 o1 = {v1x + q1.x, v1y + q1.y};
                *(float2*)(C + (size_t)rr0 * ldc + col) = o0;
                *(float2*)(C + (size_t)rr1 * ldc + col) = o1;
            }
        }
    }
}

// ---------------- O-proj GEMM: f16-accum probe (rate experiment) -----------
// CTA 128x128, 16 warps, warp tile 32x32, f16 C-fragments flushed to fp32
// every 8 chunks (256 K). Output fp32 + bias + residual.
__global__ void __launch_bounds__(GTHR, 1) gemm_f16acc(
    const __half* __restrict__ A,
    const __half* __restrict__ B,
    const float* __restrict__ bias,
    const float* __restrict__ res,
    float* __restrict__ C)
{
    extern __shared__ char smem[];
    uint32_t sb = s2u(smem);
    int tid = threadIdx.x;
    int w = tid >> 5, l = tid & 31;
    int bm = blockIdx.y * OBM;
    int bn = blockIdx.x * OBN;
    int wm = (w & 3) * 32;
    int wn = (w >> 2) * 32;

    // loads: 256 rows x 4 chunks / 512 thr = 2 consecutive chunks each
    int r0 = tid >> 1;          // 0..255 (A rows 0..127, B rows 128..255)
    int c2 = (tid & 1) * 2;     // chunk pair 0 or 2
    const __half* p0 = (r0 < 128)
        ? A + (size_t)(bm + r0) * EMB + c2 * 8
        : B + (size_t)(bn + r0 - 128) * EMB + c2 * 8;
    uint32_t d0 = (uint32_t)r0 * ROWB + c2 * 16;

    uint32_t hacc[2][4][2];
    float facc[2][4][4];
    #pragma unroll
    for (int i = 0; i < 2; i++)
        #pragma unroll
        for (int j = 0; j < 4; j++) {
            hacc[i][j][0] = 0u; hacc[i][j][1] = 0u;
            #pragma unroll
            for (int t = 0; t < 4; t++) facc[i][j][t] = 0.f;
        }

    #pragma unroll
    for (int c = 0; c < STAGES - 1; c++) {
        uint32_t stg = sb + c * OSTGB;
        cp16(stg + d0, p0); cp16(stg + d0 + 16, p0 + 8);
        p0 += GBK;
        CP_COMMIT();
    }

    uint32_t arow = (uint32_t)(wm + (l & 15)) * ROWB + ((l >> 4) << 4);
    uint32_t brow = (uint32_t)(128 + wn + (l & 15)) * ROWB + ((l >> 4) << 4);

    for (int c0 = 0; c0 < NCHUNK; c0 += STAGES) {
        #pragma unroll
        for (int s = 0; s < STAGES; s++) {
            int c = c0 + s;
            asm volatile("cp.async.wait_group %0;" :: "n"(STAGES - 2) : "memory");
            __syncthreads();
            uint32_t stg = sb + (uint32_t)s * OSTGB;

            if (c + STAGES - 1 < NCHUNK) {
                uint32_t ds = sb + (uint32_t)(((unsigned)(s + STAGES - 1)) & (STAGES - 1)) * OSTGB;
                cp16(ds + d0, p0); cp16(ds + d0 + 16, p0 + 8);
                p0 += GBK;
            }
            CP_COMMIT();

            uint32_t sA = stg + arow;
            uint32_t sB = stg + brow;

            #pragma unroll
            for (int ks = 0; ks < 2; ks++) {
                uint32_t af[2][4], br[4];
                #pragma unroll
                for (int mt = 0; mt < 2; mt++)
                    ldsm4(af[mt], sA + mt * (16 * ROWB) + ks * 32);
                ldsm4(br, sB + ks * 32);     // B rows wn..wn+15
                uint32_t br2[4];
                ldsm4(br2, sB + 16 * ROWB + ks * 32);  // rows wn+16..wn+31
                #pragma unroll
                for (int mt = 0; mt < 2; mt++) {
                    mma16816h(hacc[mt][0], af[mt], br[0],  br[2]);
                    mma16816h(hacc[mt][1], af[mt], br[1],  br[3]);
                    mma16816h(hacc[mt][2], af[mt], br2[0], br2[2]);
                    mma16816h(hacc[mt][3], af[mt], br2[1], br2[3]);
                }
            }

            // flush f16 partials into fp32 every 8 chunks
            if (((c0 + s) & 7) == 7) {
                #pragma unroll
                for (int mt = 0; mt < 2; mt++)
                    #pragma unroll
                    for (int nt = 0; nt < 4; nt++) {
                        float2 lo = __half22float2(*(__half2*)&hacc[mt][nt][0]);
                        float2 hi = __half22float2(*(__half2*)&hacc[mt][nt][1]);
                        facc[mt][nt][0] += lo.x;
                        facc[mt][nt][1] += lo.y;
                        facc[mt][nt][2] += hi.x;
                        facc[mt][nt][3] += hi.y;
                        hacc[mt][nt][0] = 0u;
                        hacc[mt][nt][1] = 0u;
                    }
            }
        }
    }

    // epilogue: bias + residual, fp32 out
    int rbase = bm + wm + (l >> 2);
    int cbase = bn + wn + 2 * (l & 3);
    #pragma unroll
    for (int mt = 0; mt < 2; mt++) {
        #pragma unroll
        for (int nt = 0; nt < 4; nt++) {
            int col = cbase + nt * 8;
            float bx = bias[col], by = bias[col + 1];
            int rr0 = rbase + mt * 16;
            int rr1 = rr0 + 8;
            float2 q0 = *(const float2*)(res + (size_t)rr0 * EMB + col);
            float2 q1 = *(const float2*)(res + (size_t)rr1 * EMB + col);
            float2 o0 = {facc[mt][nt][0] + bx + q0.x, facc[mt][nt][1] + by + q0.y};
            float2 o1 = {facc[mt][nt][2] + bx + q1.x, facc[mt][nt][3] + by + q1.y};
            *(float2*)(C + (size_t)rr0 * EMB + col) = o0;
            *(float2*)(C + (size_t)rr1 * EMB + col) = o1;
        }
    }
}

// ---------------- tensor-core sliding-window attention v3 -------------------
__global__ void __launch_bounds__(512) attn_kernel(
    const __half* __restrict__ QKV,
    __half* __restrict__ O)
{
    extern __shared__ char smem[];
    int w = threadIdx.x >> 5, l = threadIdx.x & 31;
    uint32_t ku = s2u(smem) + w * KV_BYTES;          // K rows 0..31
    uint32_t vu = ku + 32 * KROWB;                   // V rows 0..31
    int s0 = blockIdx.x * 16;
    int b = blockIdx.y;
    int hoff = w * DHD;          // warp = head
    int m0 = l >> 2;             // owned rows: m0 and m0+8
    int kq = (l & 3) * 2;

    {
        int r = s0 - 16 + l; if (r < 0) r += SLEN;
        const __half* Krow = QKV + (size_t)(r * BSZ + b) * NQKV + EMB + hoff;
        const __half* Vrow = QKV + (size_t)(r * BSZ + b) * NQKV + 2 * EMB + hoff;
        #pragma unroll
        for (int i = 0; i < 8; i++)
            cp16(ku + (uint32_t)l * KROWB + i * 16, Krow + i * 8);
        CP_COMMIT();
        #pragma unroll
        for (int i = 0; i < 8; i++)
            cp16(vu + (uint32_t)l * KROWB + i * 16, Vrow + i * 8);
        CP_COMMIT();
    }

    const __half* Qb  = QKV + (size_t)((s0 + m0)     * BSZ + b) * NQKV + hoff;
    const __half* Qb8 = QKV + (size_t)((s0 + m0 + 8) * BSZ + b) * NQKV + hoff;
    uint32_t aq[4][4];
    #pragma unroll
    for (int kt = 0; kt < 4; kt++) {
        aq[kt][0] = *(const uint32_t*)(Qb  + kt * 16 + kq);
        aq[kt][1] = *(const uint32_t*)(Qb8 + kt * 16 + kq);
        aq[kt][2] = *(const uint32_t*)(Qb  + kt * 16 + kq + 8);
        aq[kt][3] = *(const uint32_t*)(Qb8 + kt * 16 + kq + 8);
    }

    asm volatile("cp.async.wait_group 1;" ::: "memory");
    __syncwarp();

    float S[4][4];
    #pragma unroll
    for (int nt = 0; nt < 4; nt++)
        #pragma unroll
        for (int i = 0; i < 4; i++) S[nt][i] = 0.f;

    uint32_t kbase = ku + (uint32_t)(l & 15) * KROWB + ((l >> 4) << 4);
    #pragma unroll
    for (int kt = 0; kt < 4; kt++) {
        uint32_t br0[4], br1[4];
        ldsm4(br0, kbase + kt * 32);
        ldsm4(br1, kbase + 16 * KROWB + kt * 32);
        mma16816(S[0], aq[kt], br0[0], br0[2]);
        mma16816(S[1], aq[kt], br0[1], br0[3]);
        mma16816(S[2], aq[kt], br1[0], br1[2]);
        mma16816(S[3], aq[kt], br1[1], br1[3]);
    }

    int c0 = (l & 3) * 2;
    #pragma unroll
    for (int nt = 0; nt < 4; nt++) {
        #pragma unroll
        for (int i = 0; i < 4; i++) {
            int qi = (i & 2) ? (m0 + 8) : m0;
            int j = nt * 8 + c0 + (i & 1);
            bool valid = (j >= qi + 1) && (j <= qi + 16);
            S[nt][i] = valid ? S[nt][i] * 0.125f : -1e30f;
        }
    }

    float mxA = -1e30f, mxB = -1e30f;
    #pragma unroll
    for (int nt = 0; nt < 4; nt++) {
        mxA = fmaxf(mxA, fmaxf(S[nt][0], S[nt][1]));
        mxB = fmaxf(mxB, fmaxf(S[nt][2], S[nt][3]));
    }
    #pragma unroll
    for (int o = 1; o <= 2; o <<= 1) {
        mxA = fmaxf(mxA, __shfl_xor_sync(0xffffffffu, mxA, o));
        mxB = fmaxf(mxB, __shfl_xor_sync(0xffffffffu, mxB, o));
    }
    float sA = 0.f, sB2 = 0.f;
    #pragma unroll
    for (int nt = 0; nt < 4; nt++) {
        S[nt][0] = __expf(S[nt][0] - mxA); sA  += S[nt][0];
        S[nt][1] = __expf(S[nt][1] - mxA); sA  += S[nt][1];
        S[nt][2] = __expf(S[nt][2] - mxB); sB2 += S[nt][2];
        S[nt][3] = __expf(S[nt][3] - mxB); sB2 += S[nt][3];
    }
    #pragma unroll
    for (int o = 1; o <= 2; o <<= 1) {
        sA  += __shfl_xor_sync(0xffffffffu, sA,  o);
        sB2 += __shfl_xor_sync(0xffffffffu, sB2, o);
    }
    float invA = 1.0f / sA, invB = 1.0f / sB2;
    #pragma unroll
    for (int nt = 0; nt < 4; nt++) {
        S[nt][0] *= invA; S[nt][1] *= invA;
        S[nt][2] *= invB; S[nt][3] *= invB;
    }

    uint32_t pa[2][4];
    #pragma unroll
    for (int kt2 = 0; kt2 < 2; kt2++) {
        __half2 h0 = __floats2half2_rn(S[2*kt2][0],   S[2*kt2][1]);
        __half2 h1 = __floats2half2_rn(S[2*kt2][2],   S[2*kt2][3]);
        __half2 h2 = __floats2half2_rn(S[2*kt2+1][0], S[2*kt2+1][1]);
        __half2 h3 = __floats2half2_rn(S[2*kt2+1][2], S[2*kt2+1][3]);
        pa[kt2][0] = *(uint32_t*)&h0;
        pa[kt2][1] = *(uint32_t*)&h1;
        pa[kt2][2] = *(uint32_t*)&h2;
        pa[kt2][3] = *(uint32_t*)&h3;
    }

    asm volatile("cp.async.wait_group 0;" ::: "memory");
    __syncwarp();

    float out[8][4];
    #pragma unroll
    for (int i = 0; i < 8; i++)
        #pragma unroll
        for (int t = 0; t < 4; t++) out[i][t] = 0.f;

    uint32_t vlane = vu + (uint32_t)(((l & 16) >> 1) + (l & 7)) * KROWB
                        + (uint32_t)(l & 8) * 2;
    #pragma unroll
    for (int kt2 = 0; kt2 < 2; kt2++) {
        #pragma unroll
        for (int ng = 0; ng < 4; ng++) {
            uint32_t br[4];
            ldsm4t(br, vlane + kt2 * (16 * KROWB) + ng * 32);
            mma16816(out[2 * ng],     pa[kt2], br[0], br[2]);
            mma16816(out[2 * ng + 1], pa[kt2], br[1], br[3]);
        }
    }

    __half* O0 = O + (size_t)((s0 + m0)     * BSZ + b) * EMB + hoff;
    __half* O8 = O + (size_t)((s0 + m0 + 8) * BSZ + b) * EMB + hoff;
    #pragma unroll
    for (int nt2 = 0; nt2 < 8; nt2++) {
        int d = nt2 * 8 + c0;
        *(__half2*)(O0 + d) = __floats2half2_rn(out[nt2][0], out[nt2][1]);
        *(__half2*)(O8 + d) = __floats2half2_rn(out[nt2][2], out[nt2][3]);
    }
}

// ---------------- launch ----------------------------------------------------
extern "C" void kernel_launch(void* const* d_in, const int* in_sizes, int n_in,
                              void* d_out, int out_size)
{
    const float* x    = (const float*)d_in[0];
    const float* ln_g = (const float*)d_in[1];
    const float* ln_b = (const float*)d_in[2];
    const float* Wq   = (const float*)d_in[3];
    const float* bq   = (const float*)d_in[4];
    const float* Wk   = (const float*)d_in[5];
    const float* bk   = (const float*)d_in[6];
    const float* Wv   = (const float*)d_in[7];
    const float* bv   = (const float*)d_in[8];
    const float* Wo   = (const float*)d_in[9];
    const float* bo   = (const float*)d_in[10];
    float* out = (float*)d_out;

    __half *xn, *att, *wh, *qkv;
    float *bias;
    cudaGetSymbolAddress((void**)&xn,   g_xn);
    cudaGetSymbolAddress((void**)&att,  g_att);
    cudaGetSymbolAddress((void**)&wh,   g_wh);
    cudaGetSymbolAddress((void**)&qkv,  g_qkv);
    cudaGetSymbolAddress((void**)&bias, g_bias);

    cudaFuncSetAttribute(gemm_mma<1>, cudaFuncAttributeMaxDynamicSharedMemorySize, GEMM_SMEM);
    cudaFuncSetAttribute(gemm_f16acc, cudaFuncAttributeMaxDynamicSharedMemorySize, OSMEM);
    cudaFuncSetAttribute(attn_kernel, cudaFuncAttributeMaxDynamicSharedMemorySize, ATTN_SMEM);

    prep_kernel<<<8204, 256>>>(x, ln_g, ln_b, Wq, Wk, Wv, Wo,
                               bq, bk, bv, wh, xn, bias);

    gemm_mma<1><<<dim3(NQKV / GBN, MTOK / GBM), GTHR, GEMM_SMEM>>>(
        xn, wh, bias, nullptr, qkv, NQKV);

    attn_kernel<<<dim3(SLEN / 16, BSZ), 512, ATTN_SMEM>>>(qkv, att);

    // output projection + residual: f16-accum rate probe
    gemm_f16acc<<<dim3(EMB / OBM, MTOK / OBM), GTHR, OSMEM>>>(
        att, wh + (size_t)3 * EMB * EMB, bo, x, out);
}

// round 16
// speedup vs baseline: 1.0465x; 1.0465x over previous
#include <cuda_runtime.h>
#include <cuda_fp16.h>
#include <cstdint>

#define SLEN 2048
#define BSZ  2
#define EMB  1024
#define NH   16
#define DHD  64
#define PFW  16
#define MTOK (SLEN*BSZ)
#define GBK  32              // K per chunk
#define NCHUNK (EMB/GBK)     // 32
#define GBM  128
#define GBN  256
#define STAGES 4
#define ROWB 80              // padded smem row bytes (64 data + 16 pad)
#define SROWS 384            // A 128 rows + B 256 rows
#define STGB (SROWS*ROWB)    // 30720
#define GEMM_SMEM (STAGES*STGB)  // 122880
#define GTHR 512
#define NQKV 3072
#define KROWB 144            // attn K/V smem row pitch (128 data + 16 pad)
#define KV_BYTES (2*32*KROWB)    // 9216 per warp (K 32 rows + V 32 rows)
#define ATTN_WARPS 8
#define ATTN_SMEM (ATTN_WARPS*KV_BYTES)  // 73728 -> 2 blocks/SM

// ---------------- scratch (static device arrays; no allocation) -------------
__device__ __align__(16) __half g_xn [MTOK*EMB];        // LN out fp16
__device__ __align__(16) __half g_att[MTOK*EMB];        // attn out fp16
__device__ __align__(16) __half g_wh [4*EMB*EMB];       // Wq|Wk|Wv|Wo fp16, [N][K]
__device__ __align__(16) __half g_qkv[MTOK*NQKV];       // fused QKV output (fp16)
__device__ float g_bias[NQKV];

// ---------------- PTX helpers ------------------------------------------------
__device__ __forceinline__ uint32_t s2u(const void* p) {
    uint32_t a;
    asm("{ .reg .u64 t; cvta.to.shared.u64 t, %1; cvt.u32.u64 %0, t; }" : "=r"(a) : "l"(p));
    return a;
}
__device__ __forceinline__ void cp16(uint32_t dst, const void* src) {
    asm volatile("cp.async.cg.shared.global [%0], [%1], 16;" :: "r"(dst), "l"(src));
}
#define CP_COMMIT() asm volatile("cp.async.commit_group;" ::: "memory")

__device__ __forceinline__ void ldsm4(uint32_t* r, uint32_t addr) {
    asm volatile("ldmatrix.sync.aligned.m8n8.x4.shared.b16 {%0,%1,%2,%3}, [%4];"
        : "=r"(r[0]), "=r"(r[1]), "=r"(r[2]), "=r"(r[3]) : "r"(addr));
}
__device__ __forceinline__ void ldsm4t(uint32_t* r, uint32_t addr) {
    asm volatile("ldmatrix.sync.aligned.m8n8.x4.trans.shared.b16 {%0,%1,%2,%3}, [%4];"
        : "=r"(r[0]), "=r"(r[1]), "=r"(r[2]), "=r"(r[3]) : "r"(addr));
}
__device__ __forceinline__ void mma16816(float* d, const uint32_t* a,
                                         uint32_t b0, uint32_t b1) {
    asm volatile("mma.sync.aligned.m16n8k16.row.col.f32.f16.f16.f32 "
        "{%0,%1,%2,%3}, {%4,%5,%6,%7}, {%8,%9}, {%0,%1,%2,%3};"
        : "+f"(d[0]), "+f"(d[1]), "+f"(d[2]), "+f"(d[3])
        : "r"(a[0]), "r"(a[1]), "r"(a[2]), "r"(a[3]), "r"(b0), "r"(b1));
}

// ---------------- merged prep: wprep (blocks 0..4095) + LN (4096..8191)
//                  + bias concat (8192..8203), one launch --------------------
__global__ void __launch_bounds__(256) prep_kernel(
    const float* __restrict__ x,
    const float* __restrict__ gamma,
    const float* __restrict__ beta,
    const float* __restrict__ W0, const float* __restrict__ W1,
    const float* __restrict__ W2, const float* __restrict__ W3,
    const float* __restrict__ bq, const float* __restrict__ bk,
    const float* __restrict__ bv,
    __half* __restrict__ Bh,
    __half* __restrict__ xn,
    float* __restrict__ bqkv)
{
    int bid = blockIdx.x;
    int tid = threadIdx.x;

    if (bid < 4096) {
        int wsel = bid >> 10;
        int t = bid & 1023;
        int n0 = (t & 31) * 32;
        int k0 = (t >> 5) * 32;
        const float* W = (wsel == 0) ? W0 : (wsel == 1) ? W1
                       : (wsel == 2) ? W2 : W3;
        __half* B = Bh + (size_t)wsel * EMB * EMB;
        __shared__ float tile[32][33];
        int tx = tid & 31;
        int ty = tid >> 5;
        #pragma unroll
        for (int r = ty; r < 32; r += 8)
            tile[r][tx] = W[(size_t)(k0 + r) * EMB + n0 + tx];
        __syncthreads();
        #pragma unroll
        for (int r = ty; r < 32; r += 8)
            B[(size_t)(n0 + r) * EMB + (k0 + tx)] = __float2half(tile[tx][r]);
    } else if (bid < 8192) {
        int row = bid - 4096;
        const float4 xv = ((const float4*)(x + (size_t)row * EMB))[tid];
        float s  = xv.x + xv.y + xv.z + xv.w;
        float s2 = xv.x*xv.x + xv.y*xv.y + xv.z*xv.z + xv.w*xv.w;
        #pragma unroll
        for (int o = 16; o > 0; o >>= 1) {
            s  += __shfl_xor_sync(0xffffffffu, s,  o);
            s2 += __shfl_xor_sync(0xffffffffu, s2, o);
        }
        __shared__ float rs[8], rs2[8];
        __shared__ float mean_s, rstd_s;
        int w = tid >> 5, l = tid & 31;
        if (l == 0) { rs[w] = s; rs2[w] = s2; }
        __syncthreads();
        if (tid == 0) {
            float ts = 0.f, ts2 = 0.f;
            #pragma unroll
            for (int i = 0; i < 8; i++) { ts += rs[i]; ts2 += rs2[i]; }
            float mean = ts * (1.0f / EMB);
            float var  = ts2 * (1.0f / EMB) - mean * mean;
            mean_s = mean;
            rstd_s = rsqrtf(var + 1e-5f);
        }
        __syncthreads();
        float mean = mean_s, r = rstd_s;
        float4 gv = ((const float4*)gamma)[tid];
        float4 bv2 = ((const float4*)beta)[tid];
        __half h[4];
        h[0] = __float2half((xv.x - mean) * r * gv.x + bv2.x);
        h[1] = __float2half((xv.y - mean) * r * gv.y + bv2.y);
        h[2] = __float2half((xv.z - mean) * r * gv.z + bv2.z);
        h[3] = __float2half((xv.w - mean) * r * gv.w + bv2.w);
        *(uint2*)(xn + (size_t)row * EMB + tid * 4) = *(uint2*)h;
    } else {
        int i = (bid - 8192) * 256 + tid;
        if (i < NQKV)
            bqkv[i] = (i < EMB) ? bq[i] : (i < 2*EMB) ? bk[i - EMB] : bv[i - 2*EMB];
    }
}

// ---------------- HMMA fp16 GEMM (fp32 accum): C = A @ B^T + bias ----------
template<int OUT_HALF>
__global__ void __launch_bounds__(GTHR, 1) gemm_mma(
    const __half* __restrict__ A,
    const __half* __restrict__ B,
    const float* __restrict__ bias,
    const float* __restrict__ res,
    void* __restrict__ Cv,
    int ldc)
{
    extern __shared__ char smem[];
    uint32_t sb = s2u(smem);
    int tid = threadIdx.x;
    int w = tid >> 5, l = tid & 31;
    int bm = blockIdx.y * GBM;
    int bn = blockIdx.x * GBN;
    int wm = (w & 3) * 32;
    int wn = (w >> 2) * 64;

    int r0 = tid >> 2;
    int ch = tid & 3;
    const __half* p0 = A + (size_t)(bm + r0) * EMB + ch * 8;
    const __half* p1 = B + (size_t)(bn + r0) * EMB + ch * 8;
    const __half* p2 = B + (size_t)(bn + r0 + 128) * EMB + ch * 8;
    uint32_t d0 = (uint32_t)r0 * ROWB + ch * 16;
    uint32_t d1 = d0 + 128 * ROWB;
    uint32_t d2 = d0 + 256 * ROWB;

    float acc[2][8][4];
    #pragma unroll
    for (int i = 0; i < 2; i++)
        #pragma unroll
        for (int j = 0; j < 8; j++)
            #pragma unroll
            for (int t = 0; t < 4; t++) acc[i][j][t] = 0.f;

    #pragma unroll
    for (int c = 0; c < STAGES - 1; c++) {
        uint32_t stg = sb + c * STGB;
        cp16(stg + d0, p0); p0 += GBK;
        cp16(stg + d1, p1); p1 += GBK;
        cp16(stg + d2, p2); p2 += GBK;
        CP_COMMIT();
    }

    uint32_t arow = (uint32_t)(wm + (l & 15)) * ROWB + ((l >> 4) << 4);
    uint32_t brow = (uint32_t)(128 + wn + (l & 15)) * ROWB + ((l >> 4) << 4);

    for (int c0 = 0; c0 < NCHUNK; c0 += STAGES) {
        #pragma unroll
        for (int s = 0; s < STAGES; s++) {
            int c = c0 + s;
            asm volatile("cp.async.wait_group %0;" :: "n"(STAGES - 2) : "memory");
            __syncthreads();
            uint32_t stg = sb + (uint32_t)s * STGB;

            if (c + STAGES - 1 < NCHUNK) {
                uint32_t ds = sb + (uint32_t)(((unsigned)(s + STAGES - 1)) & (STAGES - 1)) * STGB;
                cp16(ds + d0, p0); p0 += GBK;
                cp16(ds + d1, p1); p1 += GBK;
                cp16(ds + d2, p2); p2 += GBK;
            }
            CP_COMMIT();

            uint32_t sA = stg + arow;
            uint32_t sB = stg + brow;

            #pragma unroll
            for (int ks = 0; ks < 2; ks++) {
                uint32_t af[2][4], br[4][4];
                #pragma unroll
                for (int mt = 0; mt < 2; mt++)
                    ldsm4(af[mt], sA + mt * (16 * ROWB) + ks * 32);
                #pragma unroll
                for (int bt = 0; bt < 4; bt++)
                    ldsm4(br[bt], sB + bt * (16 * ROWB) + ks * 32);
                #pragma unroll
                for (int mt = 0; mt < 2; mt++)
                    #pragma unroll
                    for (int bt = 0; bt < 4; bt++) {
                        mma16816(acc[mt][2 * bt],     af[mt], br[bt][0], br[bt][2]);
                        mma16816(acc[mt][2 * bt + 1], af[mt], br[bt][1], br[bt][3]);
                    }
            }
        }
    }

    int rbase = bm + wm + (l >> 2);
    int cbase = bn + wn + 2 * (l & 3);
    #pragma unroll
    for (int mt = 0; mt < 2; mt++) {
        #pragma unroll
        for (int nt = 0; nt < 8; nt++) {
            int col = cbase + nt * 8;
            float bx = bias[col], by = bias[col + 1];
            int rr0 = rbase + mt * 16;
            int rr1 = rr0 + 8;
            float v0x = acc[mt][nt][0] + bx;
            float v0y = acc[mt][nt][1] + by;
            float v1x = acc[mt][nt][2] + bx;
            float v1y = acc[mt][nt][3] + by;
            if (OUT_HALF) {
                __half* C = (__half*)Cv;
                *(__half2*)(C + (size_t)rr0 * ldc + col) = __floats2half2_rn(v0x, v0y);
                *(__half2*)(C + (size_t)rr1 * ldc + col) = __floats2half2_rn(v1x, v1y);
            } else {
                float* C = (float*)Cv;
                float2 q0 = *(const float2*)(res + (size_t)rr0 * EMB + col);
                float2 q1 = *(const float2*)(res + (size_t)rr1 * EMB + col);
                float2 o0 = {v0x + q0.x, v0y + q0.y};
                float2 o1 = {v1x + q1.x, v1y + q1.y};
                *(float2*)(C + (size_t)rr0 * ldc + col) = o0;
                *(float2*)(C + (size_t)rr1 * ldc + col) = o1;
            }
        }
    }
}

// ---------------- tensor-core sliding-window attention v3.1 ----------------
// 256-thread blocks (8 warps = 8 heads), grid (SLEN/16, BSZ, 2 head-groups).
// 73.7 KB smem -> 2 blocks/SM so staging overlaps compute across blocks.
__global__ void __launch_bounds__(256) attn_kernel(
    const __half* __restrict__ QKV,
    __half* __restrict__ O)
{
    extern __shared__ char smem[];
    int w = threadIdx.x >> 5, l = threadIdx.x & 31;
    uint32_t ku = s2u(smem) + w * KV_BYTES;          // K rows 0..31
    uint32_t vu = ku + 32 * KROWB;                   // V rows 0..31
    int s0 = blockIdx.x * 16;
    int b = blockIdx.y;
    int head = blockIdx.z * ATTN_WARPS + w;
    int hoff = head * DHD;
    int m0 = l >> 2;             // owned rows: m0 and m0+8
    int kq = (l & 3) * 2;

    {
        int r = s0 - 16 + l; if (r < 0) r += SLEN;
        const __half* Krow = QKV + (size_t)(r * BSZ + b) * NQKV + EMB + hoff;
        const __half* Vrow = QKV + (size_t)(r * BSZ + b) * NQKV + 2 * EMB + hoff;
        #pragma unroll
        for (int i = 0; i < 8; i++)
            cp16(ku + (uint32_t)l * KROWB + i * 16, Krow + i * 8);
        CP_COMMIT();
        #pragma unroll
        for (int i = 0; i < 8; i++)
            cp16(vu + (uint32_t)l * KROWB + i * 16, Vrow + i * 8);
        CP_COMMIT();
    }

    const __half* Qb  = QKV + (size_t)((s0 + m0)     * BSZ + b) * NQKV + hoff;
    const __half* Qb8 = QKV + (size_t)((s0 + m0 + 8) * BSZ + b) * NQKV + hoff;
    uint32_t aq[4][4];
    #pragma unroll
    for (int kt = 0; kt < 4; kt++) {
        aq[kt][0] = *(const uint32_t*)(Qb  + kt * 16 + kq);
        aq[kt][1] = *(const uint32_t*)(Qb8 + kt * 16 + kq);
        aq[kt][2] = *(const uint32_t*)(Qb  + kt * 16 + kq + 8);
        aq[kt][3] = *(const uint32_t*)(Qb8 + kt * 16 + kq + 8);
    }

    asm volatile("cp.async.wait_group 1;" ::: "memory");
    __syncwarp();

    float S[4][4];
    #pragma unroll
    for (int nt = 0; nt < 4; nt++)
        #pragma unroll
        for (int i = 0; i < 4; i++) S[nt][i] = 0.f;

    uint32_t kbase = ku + (uint32_t)(l & 15) * KROWB + ((l >> 4) << 4);
    #pragma unroll
    for (int kt = 0; kt < 4; kt++) {
        uint32_t br0[4], br1[4];
        ldsm4(br0, kbase + kt * 32);
        ldsm4(br1, kbase + 16 * KROWB + kt * 32);
        mma16816(S[0], aq[kt], br0[0], br0[2]);
        mma16816(S[1], aq[kt], br0[1], br0[3]);
        mma16816(S[2], aq[kt], br1[0], br1[2]);
        mma16816(S[3], aq[kt], br1[1], br1[3]);
    }

    int c0 = (l & 3) * 2;
    #pragma unroll
    for (int nt = 0; nt < 4; nt++) {
        #pragma unroll
        for (int i = 0; i < 4; i++) {
            int qi = (i & 2) ? (m0 + 8) : m0;
            int j = nt * 8 + c0 + (i & 1);
            bool valid = (j >= qi + 1) && (j <= qi + 16);
            S[nt][i] = valid ? S[nt][i] * 0.125f : -1e30f;
        }
    }

    float mxA = -1e30f, mxB = -1e30f;
    #pragma unroll
    for (int nt = 0; nt < 4; nt++) {
        mxA = fmaxf(mxA, fmaxf(S[nt][0], S[nt][1]));
        mxB = fmaxf(mxB, fmaxf(S[nt][2], S[nt][3]));
    }
    #pragma unroll
    for (int o = 1; o <= 2; o <<= 1) {
        mxA = fmaxf(mxA, __shfl_xor_sync(0xffffffffu, mxA, o));
        mxB = fmaxf(mxB, __shfl_xor_sync(0xffffffffu, mxB, o));
    }
    float sA = 0.f, sB2 = 0.f;
    #pragma unroll
    for (int nt = 0; nt < 4; nt++) {
        S[nt][0] = __expf(S[nt][0] - mxA); sA  += S[nt][0];
        S[nt][1] = __expf(S[nt][1] - mxA); sA  += S[nt][1];
        S[nt][2] = __expf(S[nt][2] - mxB); sB2 += S[nt][2];
        S[nt][3] = __expf(S[nt][3] - mxB); sB2 += S[nt][3];
    }
    #pragma unroll
    for (int o = 1; o <= 2; o <<= 1) {
        sA  += __shfl_xor_sync(0xffffffffu, sA,  o);
        sB2 += __shfl_xor_sync(0xffffffffu, sB2, o);
    }
    float invA = 1.0f / sA, invB = 1.0f / sB2;
    #pragma unroll
    for (int nt = 0; nt < 4; nt++) {
        S[nt][0] *= invA; S[nt][1] *= invA;
        S[nt][2] *= invB; S[nt][3] *= invB;
    }

    uint32_t pa[2][4];
    #pragma unroll
    for (int kt2 = 0; kt2 < 2; kt2++) {
        __half2 h0 = __floats2half2_rn(S[2*kt2][0],   S[2*kt2][1]);
        __half2 h1 = __floats2half2_rn(S[2*kt2][2],   S[2*kt2][3]);
        __half2 h2 = __floats2half2_rn(S[2*kt2+1][0], S[2*kt2+1][1]);
        __half2 h3 = __floats2half2_rn(S[2*kt2+1][2], S[2*kt2+1][3]);
        pa[kt2][0] = *(uint32_t*)&h0;
        pa[kt2][1] = *(uint32_t*)&h1;
        pa[kt2][2] = *(uint32_t*)&h2;
        pa[kt2][3] = *(uint32_t*)&h3;
    }

    asm volatile("cp.async.wait_group 0;" ::: "memory");
    __syncwarp();

    float out[8][4];
    #pragma unroll
    for (int i = 0; i < 8; i++)
        #pragma unroll
        for (int t = 0; t < 4; t++) out[i][t] = 0.f;

    uint32_t vlane = vu + (uint32_t)(((l & 16) >> 1) + (l & 7)) * KROWB
                        + (uint32_t)(l & 8) * 2;
    #pragma unroll
    for (int kt2 = 0; kt2 < 2; kt2++) {
        #pragma unroll
        for (int ng = 0; ng < 4; ng++) {
            uint32_t br[4];
            ldsm4t(br, vlane + kt2 * (16 * KROWB) + ng * 32);
            mma16816(out[2 * ng],     pa[kt2], br[0], br[2]);
            mma16816(out[2 * ng + 1], pa[kt2], br[1], br[3]);
        }
    }

    __half* O0 = O + (size_t)((s0 + m0)     * BSZ + b) * EMB + hoff;
    __half* O8 = O + (size_t)((s0 + m0 + 8) * BSZ + b) * EMB + hoff;
    #pragma unroll
    for (int nt2 = 0; nt2 < 8; nt2++) {
        int d = nt2 * 8 + c0;
        *(__half2*)(O0 + d) = __floats2half2_rn(out[nt2][0], out[nt2][1]);
        *(__half2*)(O8 + d) = __floats2half2_rn(out[nt2][2], out[nt2][3]);
    }
}

// ---------------- launch ----------------------------------------------------
extern "C" void kernel_launch(void* const* d_in, const int* in_sizes, int n_in,
                              void* d_out, int out_size)
{
    const float* x    = (const float*)d_in[0];
    const float* ln_g = (const float*)d_in[1];
    const float* ln_b = (const float*)d_in[2];
    const float* Wq   = (const float*)d_in[3];
    const float* bq   = (const float*)d_in[4];
    const float* Wk   = (const float*)d_in[5];
    const float* bk   = (const float*)d_in[6];
    const float* Wv   = (const float*)d_in[7];
    const float* bv   = (const float*)d_in[8];
    const float* Wo   = (const float*)d_in[9];
    const float* bo   = (const float*)d_in[10];
    float* out = (float*)d_out;

    __half *xn, *att, *wh, *qkv;
    float *bias;
    cudaGetSymbolAddress((void**)&xn,   g_xn);
    cudaGetSymbolAddress((void**)&att,  g_att);
    cudaGetSymbolAddress((void**)&wh,   g_wh);
    cudaGetSymbolAddress((void**)&qkv,  g_qkv);
    cudaGetSymbolAddress((void**)&bias, g_bias);

    cudaFuncSetAttribute(gemm_mma<1>, cudaFuncAttributeMaxDynamicSharedMemorySize, GEMM_SMEM);
    cudaFuncSetAttribute(gemm_mma<0>, cudaFuncAttributeMaxDynamicSharedMemorySize, GEMM_SMEM);
    cudaFuncSetAttribute(attn_kernel, cudaFuncAttributeMaxDynamicSharedMemorySize, ATTN_SMEM);

    prep_kernel<<<8204, 256>>>(x, ln_g, ln_b, Wq, Wk, Wv, Wo,
                               bq, bk, bv, wh, xn, bias);

    gemm_mma<1><<<dim3(NQKV / GBN, MTOK / GBM), GTHR, GEMM_SMEM>>>(
        xn, wh, bias, nullptr, qkv, NQKV);

    attn_kernel<<<dim3(SLEN / 16, BSZ, NH / ATTN_WARPS), 256, ATTN_SMEM>>>(qkv, att);

    gemm_mma<0><<<dim3(EMB / GBN, MTOK / GBM), GTHR, GEMM_SMEM>>>(
        att, wh + (size_t)3 * EMB * EMB, bo, x, out, EMB);
}

// round 17
// speedup vs baseline: 1.1048x; 1.0558x over previous
#include <cuda_runtime.h>
#include <cuda_fp16.h>
#include <cstdint>

#define SLEN 2048
#define BSZ  2
#define EMB  1024
#define NH   16
#define DHD  64
#define PFW  16
#define MTOK (SLEN*BSZ)
#define GBK  32              // K per chunk
#define NCHUNK (EMB/GBK)     // 32
#define GBM  128
#define GBN  256
#define STAGES 4
#define ROWB 80              // A smem row bytes (64 data + 16 pad)
#define BPITCH 528           // B smem k-row pitch (512 data + 16 pad)
#define ASTGB (GBM*ROWB)     // 10240
#define STGB (ASTGB + GBK*BPITCH)   // 27136
#define GEMM_SMEM (STAGES*STGB)     // 108544
#define GTHR 512
#define NQKV 3072
#define KROWB 144            // attn K/V smem row pitch (128 data + 16 pad)
#define KV_BYTES (2*32*KROWB)    // 9216 per warp
#define ATTN_SMEM (16*KV_BYTES)  // 147456

// ---------------- scratch (static device arrays; no allocation) -------------
__device__ __align__(16) __half g_xn [MTOK*EMB];        // LN out fp16
__device__ __align__(16) __half g_att[MTOK*EMB];        // attn out fp16
__device__ __align__(16) __half g_whq[EMB*NQKV];        // fused Wq|Wk|Wv fp16, [K][3N]
__device__ __align__(16) __half g_who[EMB*EMB];         // Wo fp16, [K][N]
__device__ __align__(16) __half g_qkv[MTOK*NQKV];       // fused QKV output (fp16)
__device__ float g_bias[NQKV];

// ---------------- PTX helpers ------------------------------------------------
__device__ __forceinline__ uint32_t s2u(const void* p) {
    uint32_t a;
    asm("{ .reg .u64 t; cvta.to.shared.u64 t, %1; cvt.u32.u64 %0, t; }" : "=r"(a) : "l"(p));
    return a;
}
__device__ __forceinline__ void cp16(uint32_t dst, const void* src) {
    asm volatile("cp.async.cg.shared.global [%0], [%1], 16;" :: "r"(dst), "l"(src));
}
#define CP_COMMIT() asm volatile("cp.async.commit_group;" ::: "memory")

__device__ __forceinline__ void ldsm4(uint32_t* r, uint32_t addr) {
    asm volatile("ldmatrix.sync.aligned.m8n8.x4.shared.b16 {%0,%1,%2,%3}, [%4];"
        : "=r"(r[0]), "=r"(r[1]), "=r"(r[2]), "=r"(r[3]) : "r"(addr));
}
__device__ __forceinline__ void ldsm4t(uint32_t* r, uint32_t addr) {
    asm volatile("ldmatrix.sync.aligned.m8n8.x4.trans.shared.b16 {%0,%1,%2,%3}, [%4];"
        : "=r"(r[0]), "=r"(r[1]), "=r"(r[2]), "=r"(r[3]) : "r"(addr));
}
__device__ __forceinline__ void mma16816(float* d, const uint32_t* a,
                                         uint32_t b0, uint32_t b1) {
    asm volatile("mma.sync.aligned.m16n8k16.row.col.f32.f16.f16.f32 "
        "{%0,%1,%2,%3}, {%4,%5,%6,%7}, {%8,%9}, {%0,%1,%2,%3};"
        : "+f"(d[0]), "+f"(d[1]), "+f"(d[2]), "+f"(d[3])
        : "r"(a[0]), "r"(a[1]), "r"(a[2]), "r"(a[3]), "r"(b0), "r"(b1));
}

// ---------------- merged prep: weight convert (0..4095) + LN (4096..8191)
//                  + bias concat (8192..8203), one launch --------------------
// Weight part: pure streaming fp32 -> fp16, NO transpose (block = one k-row).
__global__ void __launch_bounds__(256) prep_kernel(
    const float* __restrict__ x,
    const float* __restrict__ gamma,
    const float* __restrict__ beta,
    const float* __restrict__ W0, const float* __restrict__ W1,
    const float* __restrict__ W2, const float* __restrict__ W3,
    const float* __restrict__ bq, const float* __restrict__ bk,
    const float* __restrict__ bv,
    __half* __restrict__ Whq,
    __half* __restrict__ Who,
    __half* __restrict__ xn,
    float* __restrict__ bqkv)
{
    int bid = blockIdx.x;
    int tid = threadIdx.x;

    if (bid < 4096) {
        int wsel = bid >> 10;
        int k = bid & 1023;
        const float* W = (wsel == 0) ? W0 : (wsel == 1) ? W1
                       : (wsel == 2) ? W2 : W3;
        float4 v = *(const float4*)(W + (size_t)k * EMB + tid * 4);
        __half h[4];
        h[0] = __float2half(v.x); h[1] = __float2half(v.y);
        h[2] = __float2half(v.z); h[3] = __float2half(v.w);
        __half* dst = (wsel < 3)
            ? Whq + (size_t)k * NQKV + wsel * EMB + tid * 4
            : Who + (size_t)k * EMB + tid * 4;
        *(uint2*)dst = *(uint2*)h;
    } else if (bid < 8192) {
        int row = bid - 4096;
        const float4 xv = ((const float4*)(x + (size_t)row * EMB))[tid];
        float s  = xv.x + xv.y + xv.z + xv.w;
        float s2 = xv.x*xv.x + xv.y*xv.y + xv.z*xv.z + xv.w*xv.w;
        #pragma unroll
        for (int o = 16; o > 0; o >>= 1) {
            s  += __shfl_xor_sync(0xffffffffu, s,  o);
            s2 += __shfl_xor_sync(0xffffffffu, s2, o);
        }
        __shared__ float rs[8], rs2[8];
        __shared__ float mean_s, rstd_s;
        int w = tid >> 5, l = tid & 31;
        if (l == 0) { rs[w] = s; rs2[w] = s2; }
        __syncthreads();
        if (tid == 0) {
            float ts = 0.f, ts2 = 0.f;
            #pragma unroll
            for (int i = 0; i < 8; i++) { ts += rs[i]; ts2 += rs2[i]; }
            float mean = ts * (1.0f / EMB);
            float var  = ts2 * (1.0f / EMB) - mean * mean;
            mean_s = mean;
            rstd_s = rsqrtf(var + 1e-5f);
        }
        __syncthreads();
        float mean = mean_s, r = rstd_s;
        float4 gv = ((const float4*)gamma)[tid];
        float4 bv2 = ((const float4*)beta)[tid];
        __half h[4];
        h[0] = __float2half((xv.x - mean) * r * gv.x + bv2.x);
        h[1] = __float2half((xv.y - mean) * r * gv.y + bv2.y);
        h[2] = __float2half((xv.z - mean) * r * gv.z + bv2.z);
        h[3] = __float2half((xv.w - mean) * r * gv.w + bv2.w);
        *(uint2*)(xn + (size_t)row * EMB + tid * 4) = *(uint2*)h;
    } else {
        int i = (bid - 8192) * 256 + tid;
        if (i < NQKV)
            bqkv[i] = (i < EMB) ? bq[i] : (i < 2*EMB) ? bk[i - EMB] : bv[i - 2*EMB];
    }
}

// ---------------- HMMA fp16 GEMM: C = A @ W + bias (+res) -------------------
// A: [M, 1024] fp16 (k-contiguous). W: [1024, N] fp16 (n-contiguous, ldb).
// CTA tile 128x256, 16 warps, warp tile 32x64, 4-stage cp.async.
// B fragments via ldmatrix.trans on [k-rows x n-cols] smem tiles.
template<int OUT_HALF>
__global__ void __launch_bounds__(GTHR, 1) gemm_mma(
    const __half* __restrict__ A,
    const __half* __restrict__ Bw,
    const float* __restrict__ bias,
    const float* __restrict__ res,
    void* __restrict__ Cv,
    int ldb, int ldc)
{
    extern __shared__ char smem[];
    uint32_t sb = s2u(smem);
    int tid = threadIdx.x;
    int w = tid >> 5, l = tid & 31;
    int bm = blockIdx.y * GBM;
    int bn = blockIdx.x * GBN;
    int wm = (w & 3) * 32;
    int wn = (w >> 2) * 64;

    // A loads: 128 rows x 4 16B-chunks = 512 slots = 512 threads
    int ra = tid >> 2, ca = tid & 3;
    const __half* p0 = A + (size_t)(bm + ra) * EMB + ca * 8;
    uint32_t d0 = (uint32_t)ra * ROWB + ca * 16;
    // B loads: 32 k-rows x 32 16B-chunks = 1024 slots = 2 per thread
    int rb = tid >> 5, cb = tid & 31;              // rows 0..15
    const __half* p1 = Bw + (size_t)rb * ldb + bn + cb * 8;          // row rb
    const __half* p2 = Bw + (size_t)(rb + 16) * ldb + bn + cb * 8;   // row rb+16
    uint32_t d1 = (uint32_t)(ASTGB) + rb * BPITCH + cb * 16;
    uint32_t d2 = d1 + 16 * BPITCH;
    size_t bstep = (size_t)GBK * ldb;

    float acc[2][8][4];
    #pragma unroll
    for (int i = 0; i < 2; i++)
        #pragma unroll
        for (int j = 0; j < 8; j++)
            #pragma unroll
            for (int t = 0; t < 4; t++) acc[i][j][t] = 0.f;

    #pragma unroll
    for (int c = 0; c < STAGES - 1; c++) {
        uint32_t stg = sb + c * STGB;
        cp16(stg + d0, p0); p0 += GBK;
        cp16(stg + d1, p1); p1 += bstep;
        cp16(stg + d2, p2); p2 += bstep;
        CP_COMMIT();
    }

    uint32_t arow = (uint32_t)(wm + (l & 15)) * ROWB + ((l >> 4) << 4);
    // ldsm4t lane addressing (validated in attention P.V path)
    uint32_t bvl = (uint32_t)ASTGB
                 + (uint32_t)(((l & 16) >> 1) + (l & 7)) * BPITCH
                 + (uint32_t)(l & 8) * 2 + (uint32_t)wn * 2;

    for (int c0 = 0; c0 < NCHUNK; c0 += STAGES) {
        #pragma unroll
        for (int s = 0; s < STAGES; s++) {
            int c = c0 + s;
            asm volatile("cp.async.wait_group %0;" :: "n"(STAGES - 2) : "memory");
            __syncthreads();
            uint32_t stg = sb + (uint32_t)s * STGB;

            if (c + STAGES - 1 < NCHUNK) {
                uint32_t ds = sb + (uint32_t)(((unsigned)(s + STAGES - 1)) & (STAGES - 1)) * STGB;
                cp16(ds + d0, p0); p0 += GBK;
                cp16(ds + d1, p1); p1 += bstep;
                cp16(ds + d2, p2); p2 += bstep;
            }
            CP_COMMIT();

            uint32_t sA = stg + arow;
            uint32_t sBl = stg + bvl;

            #pragma unroll
            for (int kt2 = 0; kt2 < 2; kt2++) {
                uint32_t af[2][4];
                #pragma unroll
                for (int mt = 0; mt < 2; mt++)
                    ldsm4(af[mt], sA + mt * (16 * ROWB) + kt2 * 32);
                #pragma unroll
                for (int ng = 0; ng < 4; ng++) {
                    uint32_t br[4];
                    ldsm4t(br, sBl + kt2 * (16 * BPITCH) + ng * 32);
                    #pragma unroll
                    for (int mt = 0; mt < 2; mt++) {
                        mma16816(acc[mt][2 * ng],     af[mt], br[0], br[2]);
                        mma16816(acc[mt][2 * ng + 1], af[mt], br[1], br[3]);
                    }
                }
            }
        }
    }

    int rbase = bm + wm + (l >> 2);
    int cbase = bn + wn + 2 * (l & 3);
    #pragma unroll
    for (int mt = 0; mt < 2; mt++) {
        #pragma unroll
        for (int nt = 0; nt < 8; nt++) {
            int col = cbase + nt * 8;
            float bx = bias[col], by = bias[col + 1];
            int rr0 = rbase + mt * 16;
            int rr1 = rr0 + 8;
            float v0x = acc[mt][nt][0] + bx;
            float v0y = acc[mt][nt][1] + by;
            float v1x = acc[mt][nt][2] + bx;
            float v1y = acc[mt][nt][3] + by;
            if (OUT_HALF) {
                __half* C = (__half*)Cv;
                *(__half2*)(C + (size_t)rr0 * ldc + col) = __floats2half2_rn(v0x, v0y);
                *(__half2*)(C + (size_t)rr1 * ldc + col) = __floats2half2_rn(v1x, v1y);
            } else {
                float* C = (float*)Cv;
                float2 q0 = *(const float2*)(res + (size_t)rr0 * EMB + col);
                float2 q1 = *(const float2*)(res + (size_t)rr1 * EMB + col);
                float2 o0 = {v0x + q0.x, v0y + q0.y};
                float2 o1 = {v1x + q1.x, v1y + q1.y};
                *(float2*)(C + (size_t)rr0 * ldc + col) = o0;
                *(float2*)(C + (size_t)rr1 * ldc + col) = o1;
            }
        }
    }
}

// ---------------- tensor-core sliding-window attention (R14-validated) ------
__global__ void __launch_bounds__(512) attn_kernel(
    const __half* __restrict__ QKV,
    __half* __restrict__ O)
{
    extern __shared__ char smem[];
    int w = threadIdx.x >> 5, l = threadIdx.x & 31;
    uint32_t ku = s2u(smem) + w * KV_BYTES;
    uint32_t vu = ku + 32 * KROWB;
    int s0 = blockIdx.x * 16;
    int b = blockIdx.y;
    int hoff = w * DHD;
    int m0 = l >> 2;
    int kq = (l & 3) * 2;

    {
        int r = s0 - 16 + l; if (r < 0) r += SLEN;
        const __half* Krow = QKV + (size_t)(r * BSZ + b) * NQKV + EMB + hoff;
        const __half* Vrow = QKV + (size_t)(r * BSZ + b) * NQKV + 2 * EMB + hoff;
        #pragma unroll
        for (int i = 0; i < 8; i++)
            cp16(ku + (uint32_t)l * KROWB + i * 16, Krow + i * 8);
        CP_COMMIT();
        #pragma unroll
        for (int i = 0; i < 8; i++)
            cp16(vu + (uint32_t)l * KROWB + i * 16, Vrow + i * 8);
        CP_COMMIT();
    }

    const __half* Qb  = QKV + (size_t)((s0 + m0)     * BSZ + b) * NQKV + hoff;
    const __half* Qb8 = QKV + (size_t)((s0 + m0 + 8) * BSZ + b) * NQKV + hoff;
    uint32_t aq[4][4];
    #pragma unroll
    for (int kt = 0; kt < 4; kt++) {
        aq[kt][0] = *(const uint32_t*)(Qb  + kt * 16 + kq);
        aq[kt][1] = *(const uint32_t*)(Qb8 + kt * 16 + kq);
        aq[kt][2] = *(const uint32_t*)(Qb  + kt * 16 + kq + 8);
        aq[kt][3] = *(const uint32_t*)(Qb8 + kt * 16 + kq + 8);
    }

    asm volatile("cp.async.wait_group 1;" ::: "memory");
    __syncwarp();

    float S[4][4];
    #pragma unroll
    for (int nt = 0; nt < 4; nt++)
        #pragma unroll
        for (int i = 0; i < 4; i++) S[nt][i] = 0.f;

    uint32_t kbase = ku + (uint32_t)(l & 15) * KROWB + ((l >> 4) << 4);
    #pragma unroll
    for (int kt = 0; kt < 4; kt++) {
        uint32_t br0[4], br1[4];
        ldsm4(br0, kbase + kt * 32);
        ldsm4(br1, kbase + 16 * KROWB + kt * 32);
        mma16816(S[0], aq[kt], br0[0], br0[2]);
        mma16816(S[1], aq[kt], br0[1], br0[3]);
        mma16816(S[2], aq[kt], br1[0], br1[2]);
        mma16816(S[3], aq[kt], br1[1], br1[3]);
    }

    int c0 = (l & 3) * 2;
    #pragma unroll
    for (int nt = 0; nt < 4; nt++) {
        #pragma unroll
        for (int i = 0; i < 4; i++) {
            int qi = (i & 2) ? (m0 + 8) : m0;
            int j = nt * 8 + c0 + (i & 1);
            bool valid = (j >= qi + 1) && (j <= qi + 16);
            S[nt][i] = valid ? S[nt][i] * 0.125f : -1e30f;
        }
    }

    float mxA = -1e30f, mxB = -1e30f;
    #pragma unroll
    for (int nt = 0; nt < 4; nt++) {
        mxA = fmaxf(mxA, fmaxf(S[nt][0], S[nt][1]));
        mxB = fmaxf(mxB, fmaxf(S[nt][2], S[nt][3]));
    }
    #pragma unroll
    for (int o = 1; o <= 2; o <<= 1) {
        mxA = fmaxf(mxA, __shfl_xor_sync(0xffffffffu, mxA, o));
        mxB = fmaxf(mxB, __shfl_xor_sync(0xffffffffu, mxB, o));
    }
    float sA = 0.f, sB2 = 0.f;
    #pragma unroll
    for (int nt = 0; nt < 4; nt++) {
        S[nt][0] = __expf(S[nt][0] - mxA); sA  += S[nt][0];
        S[nt][1] = __expf(S[nt][1] - mxA); sA  += S[nt][1];
        S[nt][2] = __expf(S[nt][2] - mxB); sB2 += S[nt][2];
        S[nt][3] = __expf(S[nt][3] - mxB); sB2 += S[nt][3];
    }
    #pragma unroll
    for (int o = 1; o <= 2; o <<= 1) {
        sA  += __shfl_xor_sync(0xffffffffu, sA,  o);
        sB2 += __shfl_xor_sync(0xffffffffu, sB2, o);
    }
    float invA = 1.0f / sA, invB = 1.0f / sB2;
    #pragma unroll
    for (int nt = 0; nt < 4; nt++) {
        S[nt][0] *= invA; S[nt][1] *= invA;
        S[nt][2] *= invB; S[nt][3] *= invB;
    }

    uint32_t pa[2][4];
    #pragma unroll
    for (int kt2 = 0; kt2 < 2; kt2++) {
        __half2 h0 = __floats2half2_rn(S[2*kt2][0],   S[2*kt2][1]);
        __half2 h1 = __floats2half2_rn(S[2*kt2][2],   S[2*kt2][3]);
        __half2 h2 = __floats2half2_rn(S[2*kt2+1][0], S[2*kt2+1][1]);
        __half2 h3 = __floats2half2_rn(S[2*kt2+1][2], S[2*kt2+1][3]);
        pa[kt2][0] = *(uint32_t*)&h0;
        pa[kt2][1] = *(uint32_t*)&h1;
        pa[kt2][2] = *(uint32_t*)&h2;
        pa[kt2][3] = *(uint32_t*)&h3;
    }

    asm volatile("cp.async.wait_group 0;" ::: "memory");
    __syncwarp();

    float out[8][4];
    #pragma unroll
    for (int i = 0; i < 8; i++)
        #pragma unroll
        for (int t = 0; t < 4; t++) out[i][t] = 0.f;

    uint32_t vlane = vu + (uint32_t)(((l & 16) >> 1) + (l & 7)) * KROWB
                        + (uint32_t)(l & 8) * 2;
    #pragma unroll
    for (int kt2 = 0; kt2 < 2; kt2++) {
        #pragma unroll
        for (int ng = 0; ng < 4; ng++) {
            uint32_t br[4];
            ldsm4t(br, vlane + kt2 * (16 * KROWB) + ng * 32);
            mma16816(out[2 * ng],     pa[kt2], br[0], br[2]);
            mma16816(out[2 * ng + 1], pa[kt2], br[1], br[3]);
        }
    }

    __half* O0 = O + (size_t)((s0 + m0)     * BSZ + b) * EMB + hoff;
    __half* O8 = O + (size_t)((s0 + m0 + 8) * BSZ + b) * EMB + hoff;
    #pragma unroll
    for (int nt2 = 0; nt2 < 8; nt2++) {
        int d = nt2 * 8 + c0;
        *(__half2*)(O0 + d) = __floats2half2_rn(out[nt2][0], out[nt2][1]);
        *(__half2*)(O8 + d) = __floats2half2_rn(out[nt2][2], out[nt2][3]);
    }
}

// ---------------- launch ----------------------------------------------------
extern "C" void kernel_launch(void* const* d_in, const int* in_sizes, int n_in,
                              void* d_out, int out_size)
{
    const float* x    = (const float*)d_in[0];
    const float* ln_g = (const float*)d_in[1];
    const float* ln_b = (const float*)d_in[2];
    const float* Wq   = (const float*)d_in[3];
    const float* bq   = (const float*)d_in[4];
    const float* Wk   = (const float*)d_in[5];
    const float* bk   = (const float*)d_in[6];
    const float* Wv   = (const float*)d_in[7];
    const float* bv   = (const float*)d_in[8];
    const float* Wo   = (const float*)d_in[9];
    const float* bo   = (const float*)d_in[10];
    float* out = (float*)d_out;

    __half *xn, *att, *whq, *who, *qkv;
    float *bias;
    cudaGetSymbolAddress((void**)&xn,   g_xn);
    cudaGetSymbolAddress((void**)&att,  g_att);
    cudaGetSymbolAddress((void**)&whq,  g_whq);
    cudaGetSymbolAddress((void**)&who,  g_who);
    cudaGetSymbolAddress((void**)&qkv,  g_qkv);
    cudaGetSymbolAddress((void**)&bias, g_bias);

    cudaFuncSetAttribute(gemm_mma<1>, cudaFuncAttributeMaxDynamicSharedMemorySize, GEMM_SMEM);
    cudaFuncSetAttribute(gemm_mma<0>, cudaFuncAttributeMaxDynamicSharedMemorySize, GEMM_SMEM);
    cudaFuncSetAttribute(attn_kernel, cudaFuncAttributeMaxDynamicSharedMemorySize, ATTN_SMEM);

    prep_kernel<<<8204, 256>>>(x, ln_g, ln_b, Wq, Wk, Wv, Wo,
                               bq, bk, bv, whq, who, xn, bias);

    gemm_mma<1><<<dim3(NQKV / GBN, MTOK / GBM), GTHR, GEMM_SMEM>>>(
        xn, whq, bias, nullptr, qkv, NQKV, NQKV);

    attn_kernel<<<dim3(SLEN / 16, BSZ), 512, ATTN_SMEM>>>(qkv, att);

    gemm_mma<0><<<dim3(EMB / GBN, MTOK / GBM), GTHR, GEMM_SMEM>>>(
        att, who, bo, x, out, EMB, EMB);
}